// round 12
// baseline (speedup 1.0000x reference)
#include <cuda_runtime.h>
#include <cuda_fp16.h>
#include <math.h>
#include <stdint.h>

#define R_ 8
#define N_ 4096
#define F_ 256
#define B_ 16384

// ---------------- scratch (device globals; no allocs allowed) ----------------
__device__ float g_T1[(size_t)R_ * N_ * F_];   // 32 MB
__device__ float g_T2[(size_t)R_ * N_ * F_];   // 32 MB
__device__ float g_H1[(size_t)N_ * F_];        // 4 MB
__device__ float g_H2[(size_t)N_ * F_];        // 4 MB
__device__ float g_diag[R_ * F_];
__device__ unsigned g_maxbits;
__device__ float g_bscale, g_binv;
// fp16 planes: A (c folded), computed ONCE, reused by both layers
__device__ __half g_Ah[(size_t)R_ * N_ * N_];  // 256 MB
__device__ __half g_Al[(size_t)R_ * N_ * N_];  // 256 MB
// fp16 planes: B = bscale * T1, transposed to [r][o][k]
__device__ __half g_Bh[(size_t)R_ * F_ * N_];  // 16 MB
__device__ __half g_Bl[(size_t)R_ * F_ * N_];  // 16 MB

typedef unsigned long long ull;

// ---------------- scalar helpers (small GEMMs) ----------------
__device__ __forceinline__ ull ffma2(ull a, ull b, ull c) {
    ull d;
    asm("fma.rn.f32x2 %0, %1, %2, %3;" : "=l"(d) : "l"(a), "l"(b), "l"(c));
    return d;
}
__device__ __forceinline__ ull dup2(float x) {
    ull d;
    unsigned xu = __float_as_uint(x);
    asm("mov.b64 %0, {%1, %1};" : "=l"(d) : "r"(xu));
    return d;
}

// ---------------- mma / ldmatrix / cp.async helpers ----------------
__device__ __forceinline__ void mma_f16(float* d, const uint32_t* a, const uint32_t* b) {
    asm volatile(
        "mma.sync.aligned.m16n8k16.row.col.f32.f16.f16.f32 "
        "{%0,%1,%2,%3}, {%4,%5,%6,%7}, {%8,%9}, {%0,%1,%2,%3};"
        : "+f"(d[0]), "+f"(d[1]), "+f"(d[2]), "+f"(d[3])
        : "r"(a[0]), "r"(a[1]), "r"(a[2]), "r"(a[3]), "r"(b[0]), "r"(b[1]));
}
__device__ __forceinline__ void ldm4(uint32_t& r0, uint32_t& r1, uint32_t& r2, uint32_t& r3,
                                     uint32_t addr) {
    asm volatile("ldmatrix.sync.aligned.m8n8.x4.shared.b16 {%0,%1,%2,%3}, [%4];"
                 : "=r"(r0), "=r"(r1), "=r"(r2), "=r"(r3) : "r"(addr));
}
__device__ __forceinline__ void cpasync16(uint32_t dst, const void* src) {
    asm volatile("cp.async.ca.shared.global [%0], [%1], 16;" :: "r"(dst), "l"(src));
}
__device__ __forceinline__ uint32_t smem_u32(const void* p) {
    uint32_t a;
    asm("{ .reg .u64 t; cvta.to.shared.u64 t, %1; cvt.u32.u64 %0, t; }" : "=r"(a) : "l"(p));
    return a;
}
__device__ __forceinline__ void split_h(float x, __half& h, __half& l) {
    h = __float2half_rn(x);
    l = __float2half_rn(x - __half2float(h));
}

// ============================================================================
// presplit A: Ah/Al = split(c[r,n] * A[r,n,k]), layout unchanged [r][n][k]
// ============================================================================
__global__ __launch_bounds__(256)
void presplitA_kernel(const float* __restrict__ A, const float* __restrict__ c)
{
    size_t tgl = (size_t)blockIdx.x * 256 + threadIdx.x;
    size_t rn = tgl >> 9;
    int seg = (int)(tgl & 511);
    const float* src = A + rn * (size_t)N_ + seg * 8;
    float cv = __ldg(c + rn);
    float4 v0 = *(const float4*)src;
    float4 v1 = *(const float4*)(src + 4);
    float a[8] = {v0.x * cv, v0.y * cv, v0.z * cv, v0.w * cv,
                  v1.x * cv, v1.y * cv, v1.z * cv, v1.w * cv};
    __half h[8], l[8];
#pragma unroll
    for (int i = 0; i < 8; i++) split_h(a[i], h[i], l[i]);
    size_t off = rn * (size_t)N_ + seg * 8;
    *(uint4*)(g_Ah + off) = *(uint4*)h;
    *(uint4*)(g_Al + off) = *(uint4*)l;
}

// ============================================================================
// bsplit B: T1 [r][k][o] fp32 -> Bh/Bl [r][o][k] fp16 (transpose + scale + split)
// ============================================================================
__global__ void bsplitB_kernel(const float* __restrict__ T1)
{
    __shared__ float tile[32][33];
    const int tx = threadIdx.x, ty = threadIdx.y;   // (32, 8)
    const int k0 = blockIdx.x * 32, o0 = blockIdx.y * 32, r = blockIdx.z;
    const float s = g_bscale;

    const float* src = T1 + ((size_t)r * N_ + k0) * F_ + o0;
#pragma unroll
    for (int j = 0; j < 4; j++)
        tile[ty + j * 8][tx] = src[(size_t)(ty + j * 8) * F_ + tx];
    __syncthreads();

#pragma unroll
    for (int j = 0; j < 4; j++) {
        int o = ty + j * 8;
        float x = tile[tx][o] * s;
        __half h, l;
        split_h(x, h, l);
        size_t base = ((size_t)r * F_ + o0 + o) * (size_t)N_ + k0 + tx;
        g_Bh[base] = h;
        g_Bl[base] = l;
    }
}

// ============================================================================
// Scalar FFMA2 GEMM for T1 = X @ W^T, plus maxabs(T1) -> g_maxbits
// ============================================================================
__global__ __launch_bounds__(256, 2)
void gemm_small_kernel(const float* __restrict__ Abase, const float* __restrict__ Bbase,
                       float* __restrict__ Cbase, size_t strideB, size_t strideC)
{
    const int K = F_, lda = F_, ldb = F_;
    const int r = blockIdx.z;
    const float* Aop = Abase;
    const float* Bop = Bbase + (size_t)r * strideB;
    float*       Cop = Cbase + (size_t)r * strideC;

    const int n0 = blockIdx.y * 128;
    const int o0 = blockIdx.x * 128;

    __shared__ __align__(16) float As[2][16][132];
    __shared__ __align__(16) float Bs[2][16][132];

    const int tid = threadIdx.x;
    const int tx = tid & 15;
    const int ty = tid >> 4;

    ull acc[8][4];
#pragma unroll
    for (int i = 0; i < 8; i++)
#pragma unroll
        for (int j = 0; j < 4; j++) acc[i][j] = 0ull;

    float4 aL[2], bL[2];

    auto ldg_chunk = [&](int kk) {
#pragma unroll
        for (int s = 0; s < 2; s++) {
            int t = tid + s * 256;
            int n = t >> 2, kq = (t & 3) * 4;
            aL[s] = *(const float4*)(Aop + (size_t)(n0 + n) * lda + kk + kq);
        }
#pragma unroll
        for (int s = 0; s < 2; s++) {
            int t = tid + s * 256;
            int o = t >> 2, kq = (t & 3) * 4;
            bL[s] = *(const float4*)(Bop + (size_t)(o0 + o) * ldb + kk + kq);
        }
    };

    auto sts_chunk = [&](int b) {
#pragma unroll
        for (int s = 0; s < 2; s++) {
            int t = tid + s * 256;
            int n = t >> 2, kq = (t & 3) * 4;
            As[b][kq + 0][n] = aL[s].x;
            As[b][kq + 1][n] = aL[s].y;
            As[b][kq + 2][n] = aL[s].z;
            As[b][kq + 3][n] = aL[s].w;
        }
#pragma unroll
        for (int s = 0; s < 2; s++) {
            int t = tid + s * 256;
            int o = t >> 2, kq = (t & 3) * 4;
            Bs[b][kq + 0][o] = bL[s].x;
            Bs[b][kq + 1][o] = bL[s].y;
            Bs[b][kq + 2][o] = bL[s].z;
            Bs[b][kq + 3][o] = bL[s].w;
        }
    };

    auto compute_chunk = [&](int b) {
#pragma unroll
        for (int k = 0; k < 16; k++) {
            float4 a0 = *(const float4*)&As[b][k][ty * 4];
            float4 a1 = *(const float4*)&As[b][k][64 + ty * 4];
            ulonglong2 bq0 = *(const ulonglong2*)&Bs[b][k][tx * 4];
            ulonglong2 bq1 = *(const ulonglong2*)&Bs[b][k][64 + tx * 4];
            ull b0 = bq0.x, b1 = bq0.y, b2 = bq1.x, b3 = bq1.y;

            const float a0v[4] = {a0.x, a0.y, a0.z, a0.w};
            const float a1v[4] = {a1.x, a1.y, a1.z, a1.w};
#pragma unroll
            for (int i = 0; i < 4; i++) {
                ull ad = dup2(a0v[i]);
                acc[i][0] = ffma2(ad, b0, acc[i][0]);
                acc[i][1] = ffma2(ad, b1, acc[i][1]);
                acc[i][2] = ffma2(ad, b2, acc[i][2]);
                acc[i][3] = ffma2(ad, b3, acc[i][3]);
            }
#pragma unroll
            for (int i = 0; i < 4; i++) {
                ull ad = dup2(a1v[i]);
                acc[4 + i][0] = ffma2(ad, b0, acc[4 + i][0]);
                acc[4 + i][1] = ffma2(ad, b1, acc[4 + i][1]);
                acc[4 + i][2] = ffma2(ad, b2, acc[4 + i][2]);
                acc[4 + i][3] = ffma2(ad, b3, acc[4 + i][3]);
            }
        }
    };

    ldg_chunk(0);
    sts_chunk(0);
    __syncthreads();

    int buf = 0;
    for (int kk = 16; kk < K; kk += 16) {
        ldg_chunk(kk);
        compute_chunk(buf);
        sts_chunk(buf ^ 1);
        __syncthreads();
        buf ^= 1;
    }
    compute_chunk(buf);

    float mx = 0.f;
#pragma unroll
    for (int i = 0; i < 8; i++) {
        int row = n0 + ((i < 4) ? (ty * 4 + i) : (64 + ty * 4 + (i - 4)));
        float* cp = Cop + (size_t)row * F_ + o0;
        ulonglong2 v0, v1;
        v0.x = acc[i][0]; v0.y = acc[i][1];
        v1.x = acc[i][2]; v1.y = acc[i][3];
        *(ulonglong2*)(cp + tx * 4) = v0;
        *(ulonglong2*)(cp + 64 + tx * 4) = v1;
#pragma unroll
        for (int j = 0; j < 4; j++) {
            float lo = __uint_as_float((unsigned)(acc[i][j] & 0xffffffffull));
            float hi = __uint_as_float((unsigned)(acc[i][j] >> 32));
            mx = fmaxf(mx, fmaxf(fabsf(lo), fabsf(hi)));
        }
    }
#pragma unroll
    for (int o = 16; o; o >>= 1) mx = fmaxf(mx, __shfl_xor_sync(0xffffffffu, mx, o));
    if ((tid & 31) == 0) atomicMax(&g_maxbits, __float_as_uint(mx));
}

__global__ void reset_kernel() { g_maxbits = 0u; }
__global__ void finalize_kernel() {
    float mx = __uint_as_float(g_maxbits);
    int ex = 0;
    frexpf(mx, &ex);
    int e = ex > 12 ? ex - 12 : 0;   // scaled max <= 4096
    g_bscale = exp2f((float)(-e));
    g_binv   = exp2f((float)(e));
}

// ============================================================================
// big fp16 MMA GEMM: cp.async 4-stage pipeline + ldmatrix + 3-product EFT
// KEY CHANGE vs R11: MMA products issued in passes (hh over all ni, then hl,
// then lh) so same-accumulator reuse distance is 4 MMAs, not 1 — hides the
// fallback-MMA RAW latency. cp.async issue moved BEFORE compute to overlap.
// ============================================================================
#define BK 16
#define NCH (N_ / BK)               // 256
#define STG_AH 0
#define STG_AL 6144
#define STG_BH 12288
#define STG_BL 18432
#define STG_BYTES 24576
#define SMEM_BIG (4 * STG_BYTES)    // 98304

__global__ __launch_bounds__(256, 2)
void big_f16_kernel(float* __restrict__ Cout)
{
    extern __shared__ __align__(16) char smc[];
    uint32_t sb = smem_u32(smc);

    const int tid = threadIdx.x;
    const int wid = tid >> 5;
    const int lane = tid & 31;
    const int g = lane >> 2;
    const int t = lane & 3;

    const int r  = blockIdx.z;
    const int n0 = blockIdx.y * 128;
    const int o0 = blockIdx.x * 128;
    const int wm = (wid & 1) * 64;
    const int wn = (wid >> 1) * 32;

    const int row = tid >> 1, half = tid & 1;
    const size_t aoffg = ((size_t)(r * N_ + n0 + row)) * N_ + half * 8;
    const size_t boffg = ((size_t)(r * F_ + o0 + row)) * N_ + half * 8;
    const __half* sAh = g_Ah + aoffg;
    const __half* sAl = g_Al + aoffg;
    const __half* sBh = g_Bh + boffg;
    const __half* sBl = g_Bl + boffg;
    const uint32_t doff = (uint32_t)(row * 48 + half * 16);

    const uint32_t lma = (uint32_t)((wm + ((lane >> 3) & 1) * 8 + (lane & 7)) * 48
                                    + ((lane >> 4) & 1) * 16);
    const uint32_t lmb = (uint32_t)((wn + ((lane >> 4) & 1) * 8 + (lane & 7)) * 48
                                    + ((lane >> 3) & 1) * 16);

    float acc[4][4][4];
#pragma unroll
    for (int mi = 0; mi < 4; mi++)
#pragma unroll
        for (int ni = 0; ni < 4; ni++)
#pragma unroll
            for (int q = 0; q < 4; q++) acc[mi][ni][q] = 0.f;

    auto issue = [&](int stage, int k0) {
        uint32_t d = sb + stage * STG_BYTES + doff;
        cpasync16(d + STG_AH, sAh + k0);
        cpasync16(d + STG_AL, sAl + k0);
        cpasync16(d + STG_BH, sBh + k0);
        cpasync16(d + STG_BL, sBl + k0);
    };

    auto compute = [&](int stage) {
        uint32_t base = sb + stage * STG_BYTES;
        uint32_t bh[4][2], bl[4][2];
#pragma unroll
        for (int p = 0; p < 2; p++) {
            uint32_t r0, r1, r2, r3;
            ldm4(r0, r1, r2, r3, base + STG_BH + lmb + p * 768);
            bh[2 * p][0] = r0; bh[2 * p][1] = r1;
            bh[2 * p + 1][0] = r2; bh[2 * p + 1][1] = r3;
            ldm4(r0, r1, r2, r3, base + STG_BL + lmb + p * 768);
            bl[2 * p][0] = r0; bl[2 * p][1] = r1;
            bl[2 * p + 1][0] = r2; bl[2 * p + 1][1] = r3;
        }
#pragma unroll
        for (int mi = 0; mi < 4; mi++) {
            uint32_t ah[4], al[4];
            ldm4(ah[0], ah[1], ah[2], ah[3], base + STG_AH + lma + mi * 768);
            ldm4(al[0], al[1], al[2], al[3], base + STG_AL + lma + mi * 768);
            // pass 1: hi*hi — 4 independent accumulators
#pragma unroll
            for (int ni = 0; ni < 4; ni++) mma_f16(acc[mi][ni], ah, bh[ni]);
            // pass 2: hi*lo
#pragma unroll
            for (int ni = 0; ni < 4; ni++) mma_f16(acc[mi][ni], ah, bl[ni]);
            // pass 3: lo*hi
#pragma unroll
            for (int ni = 0; ni < 4; ni++) mma_f16(acc[mi][ni], al, bh[ni]);
        }
    };

    // prologue: 3 stages in flight
#pragma unroll
    for (int s = 0; s < 3; s++) {
        issue(s, s * BK);
        asm volatile("cp.async.commit_group;" ::: "memory");
    }

    for (int ch = 0; ch < NCH; ch++) {
        asm volatile("cp.async.wait_group 2;" ::: "memory");
        __syncthreads();
        int nx = ch + 3;
        if (nx < NCH) issue(nx & 3, nx * BK);   // overlap copy with MMAs below
        asm volatile("cp.async.commit_group;" ::: "memory");
        compute(ch & 3);
    }

    // epilogue: undo power-of-two B scale (exact)
    const float binv = g_binv;
    float* Cop = Cout + (size_t)r * N_ * F_;
#pragma unroll
    for (int mi = 0; mi < 4; mi++) {
#pragma unroll
        for (int ni = 0; ni < 4; ni++) {
            int row0 = n0 + wm + mi * 16 + g;
            int col  = o0 + wn + ni * 8 + t * 2;
            *(float2*)(Cop + (size_t)row0 * F_ + col) =
                make_float2(acc[mi][ni][0] * binv, acc[mi][ni][1] * binv);
            *(float2*)(Cop + (size_t)(row0 + 8) * F_ + col) =
                make_float2(acc[mi][ni][2] * binv, acc[mi][ni][3] * binv);
        }
    }
}

// ============================================================================
__global__ void reduce_kernel(float* __restrict__ Hout)
{
    int idx = blockIdx.x * 256 + threadIdx.x;
    float s = 0.f;
#pragma unroll
    for (int r = 0; r < R_; r++)
        s += g_T2[(size_t)r * N_ * F_ + idx];
    Hout[idx] = s;
}

__global__ void diag_kernel(const float* __restrict__ M)
{
    int i = blockIdx.x * 256 + threadIdx.x;
    int r = i >> 8, f = i & 255;
    g_diag[i] = M[(size_t)r * F_ * F_ + (size_t)f * F_ + f];
}

__global__ void score_kernel(const int* __restrict__ e1, const int* __restrict__ rel,
                             const int* __restrict__ e2, float* __restrict__ out)
{
    int b = blockIdx.x * 8 + (threadIdx.x >> 5);
    int lane = threadIdx.x & 31;
    const float* p = g_H2 + (size_t)e1[b] * F_;
    const float* h = g_H2 + (size_t)e2[b] * F_;
    const float* m = g_diag + rel[b] * F_;
    float s = 0.f;
#pragma unroll
    for (int i = 0; i < 2; i++) {
        int off = (lane + i * 32) * 4;
        float4 pv = *(const float4*)(p + off);
        float4 hv = *(const float4*)(h + off);
        float4 mv = *(const float4*)(m + off);
        s += pv.x * mv.x * hv.x + pv.y * mv.y * hv.y
           + pv.z * mv.z * hv.z + pv.w * mv.w * hv.w;
    }
#pragma unroll
    for (int o = 16; o; o >>= 1) s += __shfl_xor_sync(0xffffffffu, s, o);
    if (lane == 0) out[b] = 1.f / (1.f + expf(-s));
}

// ============================================================================
extern "C" void kernel_launch(void* const* d_in, const int* in_sizes, int n_in,
                              void* d_out, int out_size)
{
    const float* A   = (const float*)d_in[0];  // [R,N,N]
    const float* X   = (const float*)d_in[1];  // [N,F]
    const float* c   = (const float*)d_in[2];  // [R,N,1]
    const float* W1  = (const float*)d_in[3];  // [R,F,F]
    const float* W2  = (const float*)d_in[4];  // [R,F,F]
    const float* M   = (const float*)d_in[5];  // [R,F,F] (diagonal)
    const int*   e1  = (const int*)d_in[6];
    const int*   rel = (const int*)d_in[7];
    const int*   e2  = (const int*)d_in[8];
    float* out = (float*)d_out;

    float *T1, *T2, *H1, *H2;
    cudaGetSymbolAddress((void**)&T1, g_T1);
    cudaGetSymbolAddress((void**)&T2, g_T2);
    cudaGetSymbolAddress((void**)&H1, g_H1);
    cudaGetSymbolAddress((void**)&H2, g_H2);

    cudaFuncSetAttribute(big_f16_kernel,
                         cudaFuncAttributeMaxDynamicSharedMemorySize, SMEM_BIG);

    dim3 blk(256);
    dim3 grid_small(2, 32, 8);
    dim3 grid_big(2, 32, 8);
    dim3 grid_bsplit(N_ / 32, F_ / 32, 8), blk_bsplit(32, 8);

    const size_t sNF = (size_t)N_ * F_;
    const size_t sFF = (size_t)F_ * F_;

    // ---- A planes (c folded): once, shared by both layers ----
    presplitA_kernel<<<((size_t)R_ * N_ * N_ / 8) / 256, blk>>>(A, c);

    // ---- layer 1: H1 = sum_r (c[r] o A[r]) @ (X @ W1[r]^T) ----
    reset_kernel<<<1, 1>>>();
    gemm_small_kernel<<<grid_small, blk>>>(X, W1, T1, sFF, sNF);
    finalize_kernel<<<1, 1>>>();
    bsplitB_kernel<<<grid_bsplit, blk_bsplit>>>(T1);
    big_f16_kernel<<<grid_big, blk, SMEM_BIG>>>(T2);
    reduce_kernel<<<(N_ * F_) / 256, blk>>>(H1);

    // ---- layer 2 ----
    reset_kernel<<<1, 1>>>();
    gemm_small_kernel<<<grid_small, blk>>>(H1, W2, T1, sFF, sNF);
    finalize_kernel<<<1, 1>>>();
    bsplitB_kernel<<<grid_bsplit, blk_bsplit>>>(T1);
    big_f16_kernel<<<grid_big, blk, SMEM_BIG>>>(T2);
    reduce_kernel<<<(N_ * F_) / 256, blk>>>(H2);

    // ---- scoring: diag(M[rel]) three-way dot + sigmoid ----
    diag_kernel<<<(R_ * F_) / 256, blk>>>(M);
    score_kernel<<<B_ / 8, blk>>>(e1, rel, e2, out);
}

// round 13
// speedup vs baseline: 1.1319x; 1.1319x over previous
#include <cuda_runtime.h>
#include <cuda_fp16.h>
#include <math.h>
#include <stdint.h>

#define R_ 8
#define N_ 4096
#define F_ 256
#define B_ 16384
#define KSPLIT 2
#define KHALF (N_ / KSPLIT)         // 2048

// ---------------- scratch (device globals; no allocs allowed) ----------------
__device__ float g_T1[(size_t)R_ * N_ * F_];            // 32 MB
__device__ float g_T2[(size_t)R_ * KSPLIT * N_ * F_];   // 64 MB (split-K partials)
__device__ float g_H1[(size_t)N_ * F_];                 // 4 MB
__device__ float g_H2[(size_t)N_ * F_];                 // 4 MB
__device__ float g_diag[R_ * F_];
__device__ unsigned g_maxbits;
__device__ float g_bscale, g_binv;
// fp16 planes: A (c folded), computed ONCE, reused by both layers
__device__ __half g_Ah[(size_t)R_ * N_ * N_];  // 256 MB
__device__ __half g_Al[(size_t)R_ * N_ * N_];  // 256 MB
// fp16 planes: B = bscale * T1, transposed to [r][o][k]
__device__ __half g_Bh[(size_t)R_ * F_ * N_];  // 16 MB
__device__ __half g_Bl[(size_t)R_ * F_ * N_];  // 16 MB

typedef unsigned long long ull;

// ---------------- scalar helpers (small GEMMs) ----------------
__device__ __forceinline__ ull ffma2(ull a, ull b, ull c) {
    ull d;
    asm("fma.rn.f32x2 %0, %1, %2, %3;" : "=l"(d) : "l"(a), "l"(b), "l"(c));
    return d;
}
__device__ __forceinline__ ull dup2(float x) {
    ull d;
    unsigned xu = __float_as_uint(x);
    asm("mov.b64 %0, {%1, %1};" : "=l"(d) : "r"(xu));
    return d;
}

// ---------------- mma / ldmatrix / cp.async helpers ----------------
__device__ __forceinline__ void mma_f16(float* d, const uint32_t* a, const uint32_t* b) {
    asm volatile(
        "mma.sync.aligned.m16n8k16.row.col.f32.f16.f16.f32 "
        "{%0,%1,%2,%3}, {%4,%5,%6,%7}, {%8,%9}, {%0,%1,%2,%3};"
        : "+f"(d[0]), "+f"(d[1]), "+f"(d[2]), "+f"(d[3])
        : "r"(a[0]), "r"(a[1]), "r"(a[2]), "r"(a[3]), "r"(b[0]), "r"(b[1]));
}
__device__ __forceinline__ void ldm4(uint32_t& r0, uint32_t& r1, uint32_t& r2, uint32_t& r3,
                                     uint32_t addr) {
    asm volatile("ldmatrix.sync.aligned.m8n8.x4.shared.b16 {%0,%1,%2,%3}, [%4];"
                 : "=r"(r0), "=r"(r1), "=r"(r2), "=r"(r3) : "r"(addr));
}
__device__ __forceinline__ void cpasync16(uint32_t dst, const void* src) {
    asm volatile("cp.async.ca.shared.global [%0], [%1], 16;" :: "r"(dst), "l"(src));
}
__device__ __forceinline__ uint32_t smem_u32(const void* p) {
    uint32_t a;
    asm("{ .reg .u64 t; cvta.to.shared.u64 t, %1; cvt.u32.u64 %0, t; }" : "=r"(a) : "l"(p));
    return a;
}
__device__ __forceinline__ void split_h(float x, __half& h, __half& l) {
    h = __float2half_rn(x);
    l = __float2half_rn(x - __half2float(h));
}

// ============================================================================
// presplit A: Ah/Al = split(c[r,n] * A[r,n,k]), layout unchanged [r][n][k]
// ============================================================================
__global__ __launch_bounds__(256)
void presplitA_kernel(const float* __restrict__ A, const float* __restrict__ c)
{
    size_t tgl = (size_t)blockIdx.x * 256 + threadIdx.x;
    size_t rn = tgl >> 9;
    int seg = (int)(tgl & 511);
    const float* src = A + rn * (size_t)N_ + seg * 8;
    float cv = __ldg(c + rn);
    float4 v0 = *(const float4*)src;
    float4 v1 = *(const float4*)(src + 4);
    float a[8] = {v0.x * cv, v0.y * cv, v0.z * cv, v0.w * cv,
                  v1.x * cv, v1.y * cv, v1.z * cv, v1.w * cv};
    __half h[8], l[8];
#pragma unroll
    for (int i = 0; i < 8; i++) split_h(a[i], h[i], l[i]);
    size_t off = rn * (size_t)N_ + seg * 8;
    *(uint4*)(g_Ah + off) = *(uint4*)h;
    *(uint4*)(g_Al + off) = *(uint4*)l;
}

// ============================================================================
// bsplit B: T1 [r][k][o] fp32 -> Bh/Bl [r][o][k] fp16 (transpose + scale + split)
// ============================================================================
__global__ void bsplitB_kernel(const float* __restrict__ T1)
{
    __shared__ float tile[32][33];
    const int tx = threadIdx.x, ty = threadIdx.y;   // (32, 8)
    const int k0 = blockIdx.x * 32, o0 = blockIdx.y * 32, r = blockIdx.z;
    const float s = g_bscale;

    const float* src = T1 + ((size_t)r * N_ + k0) * F_ + o0;
#pragma unroll
    for (int j = 0; j < 4; j++)
        tile[ty + j * 8][tx] = src[(size_t)(ty + j * 8) * F_ + tx];
    __syncthreads();

#pragma unroll
    for (int j = 0; j < 4; j++) {
        int o = ty + j * 8;
        float x = tile[tx][o] * s;
        __half h, l;
        split_h(x, h, l);
        size_t base = ((size_t)r * F_ + o0 + o) * (size_t)N_ + k0 + tx;
        g_Bh[base] = h;
        g_Bl[base] = l;
    }
}

// ============================================================================
// Scalar FFMA2 GEMM for T1 = X @ W^T, plus maxabs(T1) -> g_maxbits
// ============================================================================
__global__ __launch_bounds__(256, 2)
void gemm_small_kernel(const float* __restrict__ Abase, const float* __restrict__ Bbase,
                       float* __restrict__ Cbase, size_t strideB, size_t strideC)
{
    const int K = F_, lda = F_, ldb = F_;
    const int r = blockIdx.z;
    const float* Aop = Abase;
    const float* Bop = Bbase + (size_t)r * strideB;
    float*       Cop = Cbase + (size_t)r * strideC;

    const int n0 = blockIdx.y * 128;
    const int o0 = blockIdx.x * 128;

    __shared__ __align__(16) float As[2][16][132];
    __shared__ __align__(16) float Bs[2][16][132];

    const int tid = threadIdx.x;
    const int tx = tid & 15;
    const int ty = tid >> 4;

    ull acc[8][4];
#pragma unroll
    for (int i = 0; i < 8; i++)
#pragma unroll
        for (int j = 0; j < 4; j++) acc[i][j] = 0ull;

    float4 aL[2], bL[2];

    auto ldg_chunk = [&](int kk) {
#pragma unroll
        for (int s = 0; s < 2; s++) {
            int t = tid + s * 256;
            int n = t >> 2, kq = (t & 3) * 4;
            aL[s] = *(const float4*)(Aop + (size_t)(n0 + n) * lda + kk + kq);
        }
#pragma unroll
        for (int s = 0; s < 2; s++) {
            int t = tid + s * 256;
            int o = t >> 2, kq = (t & 3) * 4;
            bL[s] = *(const float4*)(Bop + (size_t)(o0 + o) * ldb + kk + kq);
        }
    };

    auto sts_chunk = [&](int b) {
#pragma unroll
        for (int s = 0; s < 2; s++) {
            int t = tid + s * 256;
            int n = t >> 2, kq = (t & 3) * 4;
            As[b][kq + 0][n] = aL[s].x;
            As[b][kq + 1][n] = aL[s].y;
            As[b][kq + 2][n] = aL[s].z;
            As[b][kq + 3][n] = aL[s].w;
        }
#pragma unroll
        for (int s = 0; s < 2; s++) {
            int t = tid + s * 256;
            int o = t >> 2, kq = (t & 3) * 4;
            Bs[b][kq + 0][o] = bL[s].x;
            Bs[b][kq + 1][o] = bL[s].y;
            Bs[b][kq + 2][o] = bL[s].z;
            Bs[b][kq + 3][o] = bL[s].w;
        }
    };

    auto compute_chunk = [&](int b) {
#pragma unroll
        for (int k = 0; k < 16; k++) {
            float4 a0 = *(const float4*)&As[b][k][ty * 4];
            float4 a1 = *(const float4*)&As[b][k][64 + ty * 4];
            ulonglong2 bq0 = *(const ulonglong2*)&Bs[b][k][tx * 4];
            ulonglong2 bq1 = *(const ulonglong2*)&Bs[b][k][64 + tx * 4];
            ull b0 = bq0.x, b1 = bq0.y, b2 = bq1.x, b3 = bq1.y;

            const float a0v[4] = {a0.x, a0.y, a0.z, a0.w};
            const float a1v[4] = {a1.x, a1.y, a1.z, a1.w};
#pragma unroll
            for (int i = 0; i < 4; i++) {
                ull ad = dup2(a0v[i]);
                acc[i][0] = ffma2(ad, b0, acc[i][0]);
                acc[i][1] = ffma2(ad, b1, acc[i][1]);
                acc[i][2] = ffma2(ad, b2, acc[i][2]);
                acc[i][3] = ffma2(ad, b3, acc[i][3]);
            }
#pragma unroll
            for (int i = 0; i < 4; i++) {
                ull ad = dup2(a1v[i]);
                acc[4 + i][0] = ffma2(ad, b0, acc[4 + i][0]);
                acc[4 + i][1] = ffma2(ad, b1, acc[4 + i][1]);
                acc[4 + i][2] = ffma2(ad, b2, acc[4 + i][2]);
                acc[4 + i][3] = ffma2(ad, b3, acc[4 + i][3]);
            }
        }
    };

    ldg_chunk(0);
    sts_chunk(0);
    __syncthreads();

    int buf = 0;
    for (int kk = 16; kk < K; kk += 16) {
        ldg_chunk(kk);
        compute_chunk(buf);
        sts_chunk(buf ^ 1);
        __syncthreads();
        buf ^= 1;
    }
    compute_chunk(buf);

    float mx = 0.f;
#pragma unroll
    for (int i = 0; i < 8; i++) {
        int row = n0 + ((i < 4) ? (ty * 4 + i) : (64 + ty * 4 + (i - 4)));
        float* cp = Cop + (size_t)row * F_ + o0;
        ulonglong2 v0, v1;
        v0.x = acc[i][0]; v0.y = acc[i][1];
        v1.x = acc[i][2]; v1.y = acc[i][3];
        *(ulonglong2*)(cp + tx * 4) = v0;
        *(ulonglong2*)(cp + 64 + tx * 4) = v1;
#pragma unroll
        for (int j = 0; j < 4; j++) {
            float lo = __uint_as_float((unsigned)(acc[i][j] & 0xffffffffull));
            float hi = __uint_as_float((unsigned)(acc[i][j] >> 32));
            mx = fmaxf(mx, fmaxf(fabsf(lo), fabsf(hi)));
        }
    }
#pragma unroll
    for (int o = 16; o; o >>= 1) mx = fmaxf(mx, __shfl_xor_sync(0xffffffffu, mx, o));
    if ((tid & 31) == 0) atomicMax(&g_maxbits, __float_as_uint(mx));
}

__global__ void reset_kernel() { g_maxbits = 0u; }
__global__ void finalize_kernel() {
    float mx = __uint_as_float(g_maxbits);
    int ex = 0;
    frexpf(mx, &ex);
    int e = ex > 12 ? ex - 12 : 0;   // scaled max <= 4096
    g_bscale = exp2f((float)(-e));
    g_binv   = exp2f((float)(e));
}

// ============================================================================
// big fp16 MMA GEMM, SPLIT-K x2 (wave-balance fix; inner loop identical to R11):
//   z = r*2 + khalf; each CTA does K in [khalf*2048, khalf*2048+2048)
//   partials to g_T2[z-plane]; 1024 tiles -> 6.92 tiles/SM, tail ~1%.
// ============================================================================
#define BK 16
#define NCH (KHALF / BK)            // 128 chunks per CTA
#define STG_AH 0
#define STG_AL 6144
#define STG_BH 12288
#define STG_BL 18432
#define STG_BYTES 24576
#define SMEM_BIG (4 * STG_BYTES)    // 98304

__global__ __launch_bounds__(256, 2)
void big_f16_kernel(float* __restrict__ Cout)
{
    extern __shared__ __align__(16) char smc[];
    uint32_t sb = smem_u32(smc);

    const int tid = threadIdx.x;
    const int wid = tid >> 5;
    const int lane = tid & 31;
    const int g = lane >> 2;
    const int t = lane & 3;

    const int z  = blockIdx.z;          // 0..15
    const int r  = z >> 1;
    const int kh = z & 1;
    const int kbase = kh * KHALF;
    const int n0 = blockIdx.y * 128;
    const int o0 = blockIdx.x * 128;
    const int wm = (wid & 1) * 64;
    const int wn = (wid >> 1) * 32;

    const int row = tid >> 1, half = tid & 1;
    const size_t aoffg = ((size_t)(r * N_ + n0 + row)) * N_ + kbase + half * 8;
    const size_t boffg = ((size_t)(r * F_ + o0 + row)) * N_ + kbase + half * 8;
    const __half* sAh = g_Ah + aoffg;
    const __half* sAl = g_Al + aoffg;
    const __half* sBh = g_Bh + boffg;
    const __half* sBl = g_Bl + boffg;
    const uint32_t doff = (uint32_t)(row * 48 + half * 16);

    const uint32_t lma = (uint32_t)((wm + ((lane >> 3) & 1) * 8 + (lane & 7)) * 48
                                    + ((lane >> 4) & 1) * 16);
    const uint32_t lmb = (uint32_t)((wn + ((lane >> 4) & 1) * 8 + (lane & 7)) * 48
                                    + ((lane >> 3) & 1) * 16);

    float acc[4][4][4];
#pragma unroll
    for (int mi = 0; mi < 4; mi++)
#pragma unroll
        for (int ni = 0; ni < 4; ni++)
#pragma unroll
            for (int q = 0; q < 4; q++) acc[mi][ni][q] = 0.f;

    auto issue = [&](int stage, int k0) {
        uint32_t d = sb + stage * STG_BYTES + doff;
        cpasync16(d + STG_AH, sAh + k0);
        cpasync16(d + STG_AL, sAl + k0);
        cpasync16(d + STG_BH, sBh + k0);
        cpasync16(d + STG_BL, sBl + k0);
    };

    auto compute = [&](int stage) {
        uint32_t base = sb + stage * STG_BYTES;
        uint32_t bh[4][2], bl[4][2];
#pragma unroll
        for (int p = 0; p < 2; p++) {
            uint32_t r0, r1, r2, r3;
            ldm4(r0, r1, r2, r3, base + STG_BH + lmb + p * 768);
            bh[2 * p][0] = r0; bh[2 * p][1] = r1;
            bh[2 * p + 1][0] = r2; bh[2 * p + 1][1] = r3;
            ldm4(r0, r1, r2, r3, base + STG_BL + lmb + p * 768);
            bl[2 * p][0] = r0; bl[2 * p][1] = r1;
            bl[2 * p + 1][0] = r2; bl[2 * p + 1][1] = r3;
        }
#pragma unroll
        for (int mi = 0; mi < 4; mi++) {
            uint32_t ah[4], al[4];
            ldm4(ah[0], ah[1], ah[2], ah[3], base + STG_AH + lma + mi * 768);
            ldm4(al[0], al[1], al[2], al[3], base + STG_AL + lma + mi * 768);
#pragma unroll
            for (int ni = 0; ni < 4; ni++) {
                mma_f16(acc[mi][ni], ah, bh[ni]);   // hi*hi
                mma_f16(acc[mi][ni], ah, bl[ni]);   // hi*lo
                mma_f16(acc[mi][ni], al, bh[ni]);   // lo*hi
            }
        }
    };

    // prologue: 3 stages in flight
#pragma unroll
    for (int s = 0; s < 3; s++) {
        issue(s, s * BK);
        asm volatile("cp.async.commit_group;" ::: "memory");
    }

    for (int ch = 0; ch < NCH; ch++) {
        asm volatile("cp.async.wait_group 2;" ::: "memory");
        __syncthreads();
        compute(ch & 3);
        int nx = ch + 3;
        if (nx < NCH) issue(nx & 3, nx * BK);
        asm volatile("cp.async.commit_group;" ::: "memory");
    }

    // epilogue: undo power-of-two B scale (exact); write split-K partial plane
    const float binv = g_binv;
    float* Cop = Cout + (size_t)z * N_ * F_;
#pragma unroll
    for (int mi = 0; mi < 4; mi++) {
#pragma unroll
        for (int ni = 0; ni < 4; ni++) {
            int row0 = n0 + wm + mi * 16 + g;
            int col  = o0 + wn + ni * 8 + t * 2;
            *(float2*)(Cop + (size_t)row0 * F_ + col) =
                make_float2(acc[mi][ni][0] * binv, acc[mi][ni][1] * binv);
            *(float2*)(Cop + (size_t)(row0 + 8) * F_ + col) =
                make_float2(acc[mi][ni][2] * binv, acc[mi][ni][3] * binv);
        }
    }
}

// ============================================================================
// reduce: H[n,o] = sum over 16 split-K partial planes (fixed order: deterministic)
// ============================================================================
__global__ void reduce_kernel(float* __restrict__ Hout)
{
    int idx = blockIdx.x * 256 + threadIdx.x;
    float s = 0.f;
#pragma unroll
    for (int z = 0; z < R_ * KSPLIT; z++)
        s += g_T2[(size_t)z * N_ * F_ + idx];
    Hout[idx] = s;
}

__global__ void diag_kernel(const float* __restrict__ M)
{
    int i = blockIdx.x * 256 + threadIdx.x;
    int r = i >> 8, f = i & 255;
    g_diag[i] = M[(size_t)r * F_ * F_ + (size_t)f * F_ + f];
}

__global__ void score_kernel(const int* __restrict__ e1, const int* __restrict__ rel,
                             const int* __restrict__ e2, float* __restrict__ out)
{
    int b = blockIdx.x * 8 + (threadIdx.x >> 5);
    int lane = threadIdx.x & 31;
    const float* p = g_H2 + (size_t)e1[b] * F_;
    const float* h = g_H2 + (size_t)e2[b] * F_;
    const float* m = g_diag + rel[b] * F_;
    float s = 0.f;
#pragma unroll
    for (int i = 0; i < 2; i++) {
        int off = (lane + i * 32) * 4;
        float4 pv = *(const float4*)(p + off);
        float4 hv = *(const float4*)(h + off);
        float4 mv = *(const float4*)(m + off);
        s += pv.x * mv.x * hv.x + pv.y * mv.y * hv.y
           + pv.z * mv.z * hv.z + pv.w * mv.w * hv.w;
    }
#pragma unroll
    for (int o = 16; o; o >>= 1) s += __shfl_xor_sync(0xffffffffu, s, o);
    if (lane == 0) out[b] = 1.f / (1.f + expf(-s));
}

// ============================================================================
extern "C" void kernel_launch(void* const* d_in, const int* in_sizes, int n_in,
                              void* d_out, int out_size)
{
    const float* A   = (const float*)d_in[0];  // [R,N,N]
    const float* X   = (const float*)d_in[1];  // [N,F]
    const float* c   = (const float*)d_in[2];  // [R,N,1]
    const float* W1  = (const float*)d_in[3];  // [R,F,F]
    const float* W2  = (const float*)d_in[4];  // [R,F,F]
    const float* M   = (const float*)d_in[5];  // [R,F,F] (diagonal)
    const int*   e1  = (const int*)d_in[6];
    const int*   rel = (const int*)d_in[7];
    const int*   e2  = (const int*)d_in[8];
    float* out = (float*)d_out;

    float *T1, *T2, *H1, *H2;
    cudaGetSymbolAddress((void**)&T1, g_T1);
    cudaGetSymbolAddress((void**)&T2, g_T2);
    cudaGetSymbolAddress((void**)&H1, g_H1);
    cudaGetSymbolAddress((void**)&H2, g_H2);

    cudaFuncSetAttribute(big_f16_kernel,
                         cudaFuncAttributeMaxDynamicSharedMemorySize, SMEM_BIG);

    dim3 blk(256);
    dim3 grid_small(2, 32, 8);
    dim3 grid_big(2, 32, R_ * KSPLIT);   // 1024 tiles (split-K x2)
    dim3 grid_bsplit(N_ / 32, F_ / 32, 8), blk_bsplit(32, 8);

    const size_t sNF = (size_t)N_ * F_;
    const size_t sFF = (size_t)F_ * F_;

    // ---- A planes (c folded): once, shared by both layers ----
    presplitA_kernel<<<((size_t)R_ * N_ * N_ / 8) / 256, blk>>>(A, c);

    // ---- layer 1: H1 = sum_r (c[r] o A[r]) @ (X @ W1[r]^T) ----
    reset_kernel<<<1, 1>>>();
    gemm_small_kernel<<<grid_small, blk>>>(X, W1, T1, sFF, sNF);
    finalize_kernel<<<1, 1>>>();
    bsplitB_kernel<<<grid_bsplit, blk_bsplit>>>(T1);
    big_f16_kernel<<<grid_big, blk, SMEM_BIG>>>(T2);
    reduce_kernel<<<(N_ * F_) / 256, blk>>>(H1);

    // ---- layer 2 ----
    reset_kernel<<<1, 1>>>();
    gemm_small_kernel<<<grid_small, blk>>>(H1, W2, T1, sFF, sNF);
    finalize_kernel<<<1, 1>>>();
    bsplitB_kernel<<<grid_bsplit, blk_bsplit>>>(T1);
    big_f16_kernel<<<grid_big, blk, SMEM_BIG>>>(T2);
    reduce_kernel<<<(N_ * F_) / 256, blk>>>(H2);

    // ---- scoring: diag(M[rel]) three-way dot + sigmoid ----
    diag_kernel<<<(R_ * F_) / 256, blk>>>(M);
    score_kernel<<<B_ / 8, blk>>>(e1, rel, e2, out);
}